// round 2
// baseline (speedup 1.0000x reference)
#include <cuda_runtime.h>
#include <math.h>

#define NMAX 50000
#define FDIM 128

// Scratch (allocation-free rule: __device__ globals)
__device__ float g_dinv[NMAX];                     // deg, then rsqrt(deg)
__device__ float g_h1[(size_t)NMAX * FDIM];        // x @ W1
__device__ float g_a1[(size_t)NMAX * FDIM];        // propagated layer-1 activations
__device__ float g_z[NMAX];                        // relu(a1) @ W2
__device__ int   g_is64;                           // edge_index dtype flag

// ---------------- edge dtype probe ----------------
// int64 indices in [0, NMAX) have zero hi-words; int32 data reinterpreted as
// int64 packs two random indices per qword -> hi-word ~never zero 8x in a row.
__global__ void k_detect(const unsigned long long* __restrict__ ei) {
    if (threadIdx.x == 0 && blockIdx.x == 0) {
        int is64 = 1;
#pragma unroll
        for (int i = 0; i < 8; i++)
            if (ei[i] >= (unsigned long long)NMAX) is64 = 0;
        g_is64 = is64;
    }
}

__device__ __forceinline__ int edge_at(const void* ei, int is64, size_t idx) {
    return is64 ? (int)((const long long*)ei)[idx] : ((const int*)ei)[idx];
}

// ---------------- degree / normalization ----------------
__global__ void k_init_deg(int n) {
    int i = blockIdx.x * blockDim.x + threadIdx.x;
    if (i < n) g_dinv[i] = 1.0f;  // self-loop
}

__global__ void k_count(const void* __restrict__ ei, int E) {
    int e = blockIdx.x * blockDim.x + threadIdx.x;
    if (e < E) {
        int is64 = g_is64;
        atomicAdd(&g_dinv[edge_at(ei, is64, (size_t)E + e)], 1.0f);
    }
}

__global__ void k_rsqrt(int n) {
    int i = blockIdx.x * blockDim.x + threadIdx.x;
    if (i < n) g_dinv[i] = rsqrtf(g_dinv[i]);
}

// ---------------- GEMM1: h1 = x @ W1 ----------------
// 128 threads/block, 16 rows/block. W1 (64KB) + 16 x-rows (8KB) in dynamic smem.
__global__ void k_gemm1(const float* __restrict__ x, const float* __restrict__ W, int n) {
    extern __shared__ float sm[];
    float* Ws = sm;                 // 128*128
    float* xs = sm + FDIM * FDIM;   // 16*128
    int tid = threadIdx.x;

    const float4* W4 = (const float4*)W;
    float4* Ws4 = (float4*)Ws;
#pragma unroll
    for (int i = 0; i < 32; i++) Ws4[i * 128 + tid] = W4[i * 128 + tid];

    int row0 = blockIdx.x * 16;
    int nrows = n - row0; if (nrows > 16) nrows = 16;

    const float4* x4 = (const float4*)(x + (size_t)row0 * FDIM);
    float4* xs4 = (float4*)xs;
    for (int i = tid; i < nrows * 32; i += 128) xs4[i] = x4[i];
    __syncthreads();

    int j = tid;  // output column
    for (int r = 0; r < nrows; r += 4) {
        float a0 = 0.f, a1 = 0.f, a2 = 0.f, a3 = 0.f;
#pragma unroll
        for (int k = 0; k < FDIM; k += 4) {
            float4 v0 = xs4[((r + 0) * FDIM + k) >> 2];
            float4 v1 = xs4[((r + 1) * FDIM + k) >> 2];
            float4 v2 = xs4[((r + 2) * FDIM + k) >> 2];
            float4 v3 = xs4[((r + 3) * FDIM + k) >> 2];
            float w0 = Ws[(k + 0) * FDIM + j];
            float w1 = Ws[(k + 1) * FDIM + j];
            float w2 = Ws[(k + 2) * FDIM + j];
            float w3 = Ws[(k + 3) * FDIM + j];
            a0 += v0.x * w0 + v0.y * w1 + v0.z * w2 + v0.w * w3;
            a1 += v1.x * w0 + v1.y * w1 + v1.z * w2 + v1.w * w3;
            a2 += v2.x * w0 + v2.y * w1 + v2.z * w2 + v2.w * w3;
            a3 += v3.x * w0 + v3.y * w1 + v3.z * w2 + v3.w * w3;
        }
        if (r + 0 < nrows) g_h1[(size_t)(row0 + r + 0) * FDIM + j] = a0;
        if (r + 1 < nrows) g_h1[(size_t)(row0 + r + 1) * FDIM + j] = a1;
        if (r + 2 < nrows) g_h1[(size_t)(row0 + r + 2) * FDIM + j] = a2;
        if (r + 3 < nrows) g_h1[(size_t)(row0 + r + 3) * FDIM + j] = a3;
    }
}

// ---------------- a1 init: self-loop term + bias ----------------
__global__ void k_init_a1(const float* __restrict__ b1, int n) {
    int i = blockIdx.x * blockDim.x + threadIdx.x;  // over n*32 float4s
    if (i >= n * 32) return;
    int row = i >> 5;
    int c4 = i & 31;
    float d = g_dinv[row];
    float s = d * d;
    float4 h = ((const float4*)g_h1)[i];
    float4 b = ((const float4*)b1)[c4];
    float4 o;
    o.x = h.x * s + b.x;
    o.y = h.y * s + b.y;
    o.z = h.z * s + b.z;
    o.w = h.w * s + b.w;
    ((float4*)g_a1)[i] = o;
}

// ---------------- edge propagation layer 1 (warp per edge) ----------------
__global__ void k_prop1(const void* __restrict__ ei, int E) {
    int w = (blockIdx.x * blockDim.x + threadIdx.x) >> 5;
    int lane = threadIdx.x & 31;
    if (w >= E) return;
    int is64 = g_is64;
    int src = edge_at(ei, is64, (size_t)w);
    int dst = edge_at(ei, is64, (size_t)E + w);
    float norm = g_dinv[src] * g_dinv[dst];
    float4 v = ((const float4*)(g_h1 + (size_t)src * FDIM))[lane];
    v.x *= norm; v.y *= norm; v.z *= norm; v.w *= norm;
    float* addr = g_a1 + (size_t)dst * FDIM + lane * 4;
    asm volatile("red.global.add.v4.f32 [%0], {%1, %2, %3, %4};"
                 :: "l"(addr), "f"(v.x), "f"(v.y), "f"(v.z), "f"(v.w)
                 : "memory");
}

// ---------------- layer 2: z = relu(a1) @ W2; out init ----------------
__global__ void k_layer2(const float* __restrict__ W2, const float* __restrict__ b2,
                         float* __restrict__ out, int n) {
    int node = (blockIdx.x * blockDim.x + threadIdx.x) >> 5;
    int lane = threadIdx.x & 31;
    if (node >= n) return;
    float4 v = ((const float4*)(g_a1 + (size_t)node * FDIM))[lane];
    float4 w = ((const float4*)W2)[lane];
    float p = fmaxf(v.x, 0.f) * w.x + fmaxf(v.y, 0.f) * w.y +
              fmaxf(v.z, 0.f) * w.z + fmaxf(v.w, 0.f) * w.w;
#pragma unroll
    for (int o = 16; o; o >>= 1) p += __shfl_down_sync(0xFFFFFFFFu, p, o);
    if (lane == 0) {
        g_z[node] = p;
        float d = g_dinv[node];
        out[node] = p * d * d + b2[0];
    }
}

// ---------------- edge propagation layer 2 (thread per edge) ----------------
__global__ void k_prop2(const void* __restrict__ ei, float* __restrict__ out, int E) {
    int e = blockIdx.x * blockDim.x + threadIdx.x;
    if (e >= E) return;
    int is64 = g_is64;
    int src = edge_at(ei, is64, (size_t)e);
    int dst = edge_at(ei, is64, (size_t)E + e);
    atomicAdd(&out[dst], g_z[src] * g_dinv[src] * g_dinv[dst]);
}

extern "C" void kernel_launch(void* const* d_in, const int* in_sizes, int n_in,
                              void* d_out, int out_size) {
    const float* x  = (const float*)d_in[0];
    const void*  ei = d_in[1];
    const float* W1 = (const float*)d_in[2];
    const float* b1 = (const float*)d_in[3];
    const float* W2 = (const float*)d_in[4];
    const float* b2 = (const float*)d_in[5];
    float*       out = (float*)d_out;

    int n = in_sizes[0] / FDIM;   // 50000
    int E = in_sizes[1] / 2;      // 800000

    cudaFuncSetAttribute(k_gemm1, cudaFuncAttributeMaxDynamicSharedMemorySize,
                         (FDIM * FDIM + 16 * FDIM) * sizeof(float));

    k_detect<<<1, 32>>>((const unsigned long long*)ei);
    k_init_deg<<<(n + 255) / 256, 256>>>(n);
    k_count<<<(E + 255) / 256, 256>>>(ei, E);
    k_rsqrt<<<(n + 255) / 256, 256>>>(n);
    k_gemm1<<<(n + 15) / 16, 128, (FDIM * FDIM + 16 * FDIM) * sizeof(float)>>>(x, W1, n);
    k_init_a1<<<(n * 32 + 255) / 256, 256>>>(b1, n);
    k_prop1<<<(E + 7) / 8, 256>>>(ei, E);
    k_layer2<<<(n + 7) / 8, 256>>>(W2, b2, out, n);
    k_prop2<<<(E + 255) / 256, 256>>>(ei, out, E);
}

// round 3
// speedup vs baseline: 1.4528x; 1.4528x over previous
#include <cuda_runtime.h>
#include <math.h>

#define NMAX 50000
#define EMAX 800000
#define FDIM 128
#define SCAN_B 256

// Scratch (allocation-free rule: __device__ globals)
__device__ float g_dinv[NMAX];
__device__ float g_h1[(size_t)NMAX * FDIM];        // x @ W1
__device__ float g_zd[NMAX];                       // (relu(a1)@W2 + ...) * dinv
__device__ int   g_degE[NMAX];                     // edge in-degree (no self-loop)
__device__ int   g_ptr[NMAX];                      // CSR row start (exclusive scan)
__device__ int   g_fill[NMAX];                     // atomic fill cursor
__device__ int   g_esrc[EMAX];                     // CSR src per incoming edge
__device__ int   g_bsums[1024];
__device__ int   g_is64;

// ---------------- edge dtype probe ----------------
__global__ void k_detect(const unsigned long long* __restrict__ ei) {
    if (threadIdx.x == 0 && blockIdx.x == 0) {
        int is64 = 1;
#pragma unroll
        for (int i = 0; i < 8; i++)
            if (ei[i] >= (unsigned long long)NMAX) is64 = 0;
        g_is64 = is64;
    }
}

__device__ __forceinline__ int edge_at(const void* ei, int is64, size_t idx) {
    return is64 ? (int)((const long long*)ei)[idx] : ((const int*)ei)[idx];
}

// ---------------- degree histogram ----------------
__global__ void k_zero_deg(int n) {
    int i = blockIdx.x * blockDim.x + threadIdx.x;
    if (i < n) g_degE[i] = 0;
}

__global__ void k_hist(const void* __restrict__ ei, int E) {
    int e = blockIdx.x * blockDim.x + threadIdx.x;
    if (e < E) {
        int is64 = g_is64;
        atomicAdd(&g_degE[edge_at(ei, is64, (size_t)E + e)], 1);
    }
}

// ---------------- 2-level exclusive scan ----------------
__global__ void k_scan1(int n) {
    __shared__ int sm[SCAN_B];
    int i = blockIdx.x * SCAN_B + threadIdx.x;
    int v = (i < n) ? g_degE[i] : 0;
    sm[threadIdx.x] = v;
    __syncthreads();
#pragma unroll
    for (int off = 1; off < SCAN_B; off <<= 1) {
        int t = (threadIdx.x >= off) ? sm[threadIdx.x - off] : 0;
        __syncthreads();
        sm[threadIdx.x] += t;
        __syncthreads();
    }
    if (i < n) g_ptr[i] = sm[threadIdx.x];            // inclusive within block
    if (threadIdx.x == SCAN_B - 1) g_bsums[blockIdx.x] = sm[threadIdx.x];
}

__global__ void k_scan2(int nblocks) {
    __shared__ int sm[1024];
    int t = threadIdx.x;
    sm[t] = (t < nblocks) ? g_bsums[t] : 0;
    __syncthreads();
#pragma unroll
    for (int off = 1; off < 1024; off <<= 1) {
        int v = (t >= off) ? sm[t - off] : 0;
        __syncthreads();
        sm[t] += v;
        __syncthreads();
    }
    if (t < nblocks) g_bsums[t] = sm[t];              // inclusive
}

__global__ void k_scan3(int n) {
    int i = blockIdx.x * SCAN_B + threadIdx.x;
    if (i >= n) return;
    int off = (blockIdx.x > 0) ? g_bsums[blockIdx.x - 1] : 0;
    int d = g_degE[i];
    int start = off + g_ptr[i] - d;                   // exclusive
    g_ptr[i] = start;
    g_fill[i] = start;
    g_dinv[i] = rsqrtf((float)(d + 1));               // +1 self-loop
}

// ---------------- CSR scatter fill ----------------
__global__ void k_scatter(const void* __restrict__ ei, int E) {
    int e = blockIdx.x * blockDim.x + threadIdx.x;
    if (e >= E) return;
    int is64 = g_is64;
    int src = edge_at(ei, is64, (size_t)e);
    int dst = edge_at(ei, is64, (size_t)E + e);
    int pos = atomicAdd(&g_fill[dst], 1);
    g_esrc[pos] = src;
}

// ---------------- GEMM1: h1 = x @ W1 (32 rows/block) ----------------
__global__ void k_gemm1(const float* __restrict__ x, const float* __restrict__ W, int n) {
    extern __shared__ float sm[];
    float* Ws = sm;                  // 128*128
    float* xs = sm + FDIM * FDIM;    // 32*128
    int tid = threadIdx.x;

    const float4* W4 = (const float4*)W;
    float4* Ws4 = (float4*)Ws;
#pragma unroll
    for (int i = 0; i < 32; i++) Ws4[i * 128 + tid] = W4[i * 128 + tid];

    int row0 = blockIdx.x * 32;
    int nrows = n - row0; if (nrows > 32) nrows = 32;

    const float4* x4 = (const float4*)(x + (size_t)row0 * FDIM);
    float4* xs4 = (float4*)xs;
    for (int i = tid; i < nrows * 32; i += 128) xs4[i] = x4[i];
    __syncthreads();

    int j = tid;
    for (int r = 0; r < nrows; r += 4) {
        float a0 = 0.f, a1 = 0.f, a2 = 0.f, a3 = 0.f;
#pragma unroll
        for (int k = 0; k < FDIM; k += 4) {
            float4 v0 = xs4[((r + 0) * FDIM + k) >> 2];
            float4 v1 = xs4[((r + 1) * FDIM + k) >> 2];
            float4 v2 = xs4[((r + 2) * FDIM + k) >> 2];
            float4 v3 = xs4[((r + 3) * FDIM + k) >> 2];
            float w0 = Ws[(k + 0) * FDIM + j];
            float w1 = Ws[(k + 1) * FDIM + j];
            float w2 = Ws[(k + 2) * FDIM + j];
            float w3 = Ws[(k + 3) * FDIM + j];
            a0 += v0.x * w0 + v0.y * w1 + v0.z * w2 + v0.w * w3;
            a1 += v1.x * w0 + v1.y * w1 + v1.z * w2 + v1.w * w3;
            a2 += v2.x * w0 + v2.y * w1 + v2.z * w2 + v2.w * w3;
            a3 += v3.x * w0 + v3.y * w1 + v3.z * w2 + v3.w * w3;
        }
        if (r + 0 < nrows) g_h1[(size_t)(row0 + r + 0) * FDIM + j] = a0;
        if (r + 1 < nrows) g_h1[(size_t)(row0 + r + 1) * FDIM + j] = a1;
        if (r + 2 < nrows) g_h1[(size_t)(row0 + r + 2) * FDIM + j] = a2;
        if (r + 3 < nrows) g_h1[(size_t)(row0 + r + 3) * FDIM + j] = a3;
    }
}

// ---------------- fused aggregate1 + bias + relu + layer2 dot ----------------
// warp per node: acc[128] (4 floats/lane) = dinv_i^2*h1[i] + sum_j dinv_j*dinv_i*h1[src_j]
// then zd[i] = dinv_i * sum_c relu(acc_c + b1_c) * W2_c
__global__ void k_aggr1(const float* __restrict__ b1, const float* __restrict__ W2, int n) {
    int node = (blockIdx.x * blockDim.x + threadIdx.x) >> 5;
    int lane = threadIdx.x & 31;
    if (node >= n) return;

    float di = g_dinv[node];
    float4 acc = ((const float4*)(g_h1 + (size_t)node * FDIM))[lane];
    float s = di * di;
    acc.x *= s; acc.y *= s; acc.z *= s; acc.w *= s;

    int p = g_ptr[node];
    int e = p + g_degE[node];
    for (int j = p; j < e; j++) {
        int src = g_esrc[j];                 // warp-uniform broadcast
        float w = g_dinv[src] * di;
        float4 v = ((const float4*)(g_h1 + (size_t)src * FDIM))[lane];
        acc.x = fmaf(v.x, w, acc.x);
        acc.y = fmaf(v.y, w, acc.y);
        acc.z = fmaf(v.z, w, acc.z);
        acc.w = fmaf(v.w, w, acc.w);
    }

    float4 b = ((const float4*)b1)[lane];
    float4 w2 = ((const float4*)W2)[lane];
    float z = fmaxf(acc.x + b.x, 0.f) * w2.x + fmaxf(acc.y + b.y, 0.f) * w2.y +
              fmaxf(acc.z + b.z, 0.f) * w2.z + fmaxf(acc.w + b.w, 0.f) * w2.w;
#pragma unroll
    for (int o = 16; o; o >>= 1) z += __shfl_down_sync(0xFFFFFFFFu, z, o);
    if (lane == 0) g_zd[node] = z * di;
}

// ---------------- layer 2 aggregation (thread per node) ----------------
// out[i] = b2 + dinv_i * (zd[i] + sum_j zd[src_j])
__global__ void k_aggr2(const float* __restrict__ b2, float* __restrict__ out, int n) {
    int i = blockIdx.x * blockDim.x + threadIdx.x;
    if (i >= n) return;
    float acc = g_zd[i];
    int p = g_ptr[i];
    int e = p + g_degE[i];
    for (int j = p; j < e; j++) acc += g_zd[g_esrc[j]];
    out[i] = fmaf(g_dinv[i], acc, b2[0]);
}

extern "C" void kernel_launch(void* const* d_in, const int* in_sizes, int n_in,
                              void* d_out, int out_size) {
    const float* x  = (const float*)d_in[0];
    const void*  ei = d_in[1];
    const float* W1 = (const float*)d_in[2];
    const float* b1 = (const float*)d_in[3];
    const float* W2 = (const float*)d_in[4];
    const float* b2 = (const float*)d_in[5];
    float*       out = (float*)d_out;

    int n = in_sizes[0] / FDIM;   // 50000
    int E = in_sizes[1] / 2;      // 800000
    int nblocks = (n + SCAN_B - 1) / SCAN_B;

    cudaFuncSetAttribute(k_gemm1, cudaFuncAttributeMaxDynamicSharedMemorySize,
                         (FDIM * FDIM + 32 * FDIM) * sizeof(float));

    k_detect<<<1, 32>>>((const unsigned long long*)ei);
    k_zero_deg<<<nblocks, SCAN_B>>>(n);
    k_hist<<<(E + 255) / 256, 256>>>(ei, E);
    k_scan1<<<nblocks, SCAN_B>>>(n);
    k_scan2<<<1, 1024>>>(nblocks);
    k_scan3<<<nblocks, SCAN_B>>>(n);
    k_scatter<<<(E + 255) / 256, 256>>>(ei, E);
    k_gemm1<<<(n + 31) / 32, 128, (FDIM * FDIM + 32 * FDIM) * sizeof(float)>>>(x, W1, n);
    k_aggr1<<<(n + 7) / 8, 256>>>(b1, W2, n);
    k_aggr2<<<(n + 255) / 256, 256>>>(b2, out, n);
}

// round 4
// speedup vs baseline: 1.7640x; 1.2142x over previous
#include <cuda_runtime.h>
#include <math.h>

#define NMAX 50000
#define EMAX 800000
#define FDIM 128
#define SCAN_B 256
#define GROWS 64   // rows per gemm1 block

// Scratch (allocation-free rule: __device__ globals)
__device__ float g_dinv[NMAX];
__device__ float g_h1[(size_t)NMAX * FDIM];        // x @ W1
__device__ float g_zd[NMAX];                       // (relu(a1)@W2)*dinv
__device__ int   g_degE[NMAX];                     // edge in-degree (no self-loop)
__device__ int   g_ptr[NMAX];                      // CSR row start
__device__ int   g_fill[NMAX];                     // atomic fill cursor
__device__ int   g_esrc[EMAX];                     // CSR src per incoming edge
__device__ int   g_bsums[1024];
__device__ int   g_is64;

__device__ __forceinline__ int edge_at(const void* ei, int is64, size_t idx) {
    return is64 ? (int)((const long long*)ei)[idx] : ((const int*)ei)[idx];
}

// ---------------- zero degrees + edge dtype probe ----------------
__global__ void k_zero_deg(const unsigned long long* __restrict__ ei, int n) {
    int i = blockIdx.x * blockDim.x + threadIdx.x;
    if (i < n) g_degE[i] = 0;
    if (i == 0) {
        int is64 = 1;
#pragma unroll
        for (int k = 0; k < 8; k++)
            if (ei[k] >= (unsigned long long)NMAX) is64 = 0;
        g_is64 = is64;
    }
}

__global__ void k_hist(const void* __restrict__ ei, int E) {
    int e = blockIdx.x * blockDim.x + threadIdx.x;
    if (e < E) {
        int is64 = g_is64;
        atomicAdd(&g_degE[edge_at(ei, is64, (size_t)E + e)], 1);
    }
}

// ---------------- 2-level exclusive scan ----------------
__global__ void k_scan1(int n) {
    __shared__ int sm[SCAN_B];
    int i = blockIdx.x * SCAN_B + threadIdx.x;
    int v = (i < n) ? g_degE[i] : 0;
    sm[threadIdx.x] = v;
    __syncthreads();
#pragma unroll
    for (int off = 1; off < SCAN_B; off <<= 1) {
        int t = (threadIdx.x >= off) ? sm[threadIdx.x - off] : 0;
        __syncthreads();
        sm[threadIdx.x] += t;
        __syncthreads();
    }
    if (i < n) g_ptr[i] = sm[threadIdx.x];            // inclusive within block
    if (threadIdx.x == SCAN_B - 1) g_bsums[blockIdx.x] = sm[threadIdx.x];
}

__global__ void k_scan2(int nblocks) {
    __shared__ int sm[1024];
    int t = threadIdx.x;
    sm[t] = (t < nblocks) ? g_bsums[t] : 0;
    __syncthreads();
#pragma unroll
    for (int off = 1; off < 1024; off <<= 1) {
        int v = (t >= off) ? sm[t - off] : 0;
        __syncthreads();
        sm[t] += v;
        __syncthreads();
    }
    if (t < nblocks) g_bsums[t] = sm[t];              // inclusive
}

__global__ void k_scan3(int n) {
    int i = blockIdx.x * SCAN_B + threadIdx.x;
    if (i >= n) return;
    int off = (blockIdx.x > 0) ? g_bsums[blockIdx.x - 1] : 0;
    int d = g_degE[i];
    int start = off + g_ptr[i] - d;                   // exclusive
    g_ptr[i] = start;
    g_fill[i] = start;
    g_dinv[i] = rsqrtf((float)(d + 1));               // +1 self-loop
}

// ---------------- CSR scatter fill ----------------
__global__ void k_scatter(const void* __restrict__ ei, int E) {
    int e = blockIdx.x * blockDim.x + threadIdx.x;
    if (e >= E) return;
    int is64 = g_is64;
    int src = edge_at(ei, is64, (size_t)e);
    int dst = edge_at(ei, is64, (size_t)E + e);
    int pos = atomicAdd(&g_fill[dst], 1);
    g_esrc[pos] = src;
}

// ---------------- GEMM1: h1 = x @ W1 (64 rows/block) ----------------
__global__ void k_gemm1(const float* __restrict__ x, const float* __restrict__ W, int n) {
    extern __shared__ float sm[];
    float* Ws = sm;                  // 128*128
    float* xs = sm + FDIM * FDIM;    // GROWS*128
    int tid = threadIdx.x;

    const float4* W4 = (const float4*)W;
    float4* Ws4 = (float4*)Ws;
#pragma unroll
    for (int i = 0; i < 32; i++) Ws4[i * 128 + tid] = W4[i * 128 + tid];

    int row0 = blockIdx.x * GROWS;
    int nrows = n - row0; if (nrows > GROWS) nrows = GROWS;

    const float4* x4 = (const float4*)(x + (size_t)row0 * FDIM);
    float4* xs4 = (float4*)xs;
    for (int i = tid; i < nrows * 32; i += 128) xs4[i] = x4[i];
    __syncthreads();

    int j = tid;
    for (int r = 0; r < nrows; r += 4) {
        float a0 = 0.f, a1 = 0.f, a2 = 0.f, a3 = 0.f;
#pragma unroll
        for (int k = 0; k < FDIM; k += 4) {
            float4 v0 = xs4[((r + 0) * FDIM + k) >> 2];
            float4 v1 = xs4[((r + 1) * FDIM + k) >> 2];
            float4 v2 = xs4[((r + 2) * FDIM + k) >> 2];
            float4 v3 = xs4[((r + 3) * FDIM + k) >> 2];
            float w0 = Ws[(k + 0) * FDIM + j];
            float w1 = Ws[(k + 1) * FDIM + j];
            float w2 = Ws[(k + 2) * FDIM + j];
            float w3 = Ws[(k + 3) * FDIM + j];
            a0 += v0.x * w0 + v0.y * w1 + v0.z * w2 + v0.w * w3;
            a1 += v1.x * w0 + v1.y * w1 + v1.z * w2 + v1.w * w3;
            a2 += v2.x * w0 + v2.y * w1 + v2.z * w2 + v2.w * w3;
            a3 += v3.x * w0 + v3.y * w1 + v3.z * w2 + v3.w * w3;
        }
        if (r + 0 < nrows) g_h1[(size_t)(row0 + r + 0) * FDIM + j] = a0;
        if (r + 1 < nrows) g_h1[(size_t)(row0 + r + 1) * FDIM + j] = a1;
        if (r + 2 < nrows) g_h1[(size_t)(row0 + r + 2) * FDIM + j] = a2;
        if (r + 3 < nrows) g_h1[(size_t)(row0 + r + 3) * FDIM + j] = a3;
    }
}

// ---------------- fused aggregate1 + bias + relu + layer2 dot ----------------
__global__ void k_aggr1(const float* __restrict__ b1, const float* __restrict__ W2, int n) {
    int node = (blockIdx.x * blockDim.x + threadIdx.x) >> 5;
    int lane = threadIdx.x & 31;
    if (node >= n) return;

    float di = g_dinv[node];
    float4 acc = ((const float4*)(g_h1 + (size_t)node * FDIM))[lane];
    float s = di * di;
    acc.x *= s; acc.y *= s; acc.z *= s; acc.w *= s;

    int p = g_ptr[node];
    int e = p + g_degE[node];
    int j = p;
    // unroll by 4: 4 independent gathers in flight per warp
    for (; j + 4 <= e; j += 4) {
        int s0 = g_esrc[j + 0];
        int s1 = g_esrc[j + 1];
        int s2 = g_esrc[j + 2];
        int s3 = g_esrc[j + 3];
        float w0 = g_dinv[s0] * di;
        float w1 = g_dinv[s1] * di;
        float w2 = g_dinv[s2] * di;
        float w3 = g_dinv[s3] * di;
        float4 v0 = ((const float4*)(g_h1 + (size_t)s0 * FDIM))[lane];
        float4 v1 = ((const float4*)(g_h1 + (size_t)s1 * FDIM))[lane];
        float4 v2 = ((const float4*)(g_h1 + (size_t)s2 * FDIM))[lane];
        float4 v3 = ((const float4*)(g_h1 + (size_t)s3 * FDIM))[lane];
        acc.x = fmaf(v0.x, w0, acc.x); acc.y = fmaf(v0.y, w0, acc.y);
        acc.z = fmaf(v0.z, w0, acc.z); acc.w = fmaf(v0.w, w0, acc.w);
        acc.x = fmaf(v1.x, w1, acc.x); acc.y = fmaf(v1.y, w1, acc.y);
        acc.z = fmaf(v1.z, w1, acc.z); acc.w = fmaf(v1.w, w1, acc.w);
        acc.x = fmaf(v2.x, w2, acc.x); acc.y = fmaf(v2.y, w2, acc.y);
        acc.z = fmaf(v2.z, w2, acc.z); acc.w = fmaf(v2.w, w2, acc.w);
        acc.x = fmaf(v3.x, w3, acc.x); acc.y = fmaf(v3.y, w3, acc.y);
        acc.z = fmaf(v3.z, w3, acc.z); acc.w = fmaf(v3.w, w3, acc.w);
    }
    for (; j < e; j++) {
        int src = g_esrc[j];
        float w = g_dinv[src] * di;
        float4 v = ((const float4*)(g_h1 + (size_t)src * FDIM))[lane];
        acc.x = fmaf(v.x, w, acc.x); acc.y = fmaf(v.y, w, acc.y);
        acc.z = fmaf(v.z, w, acc.z); acc.w = fmaf(v.w, w, acc.w);
    }

    float4 b = ((const float4*)b1)[lane];
    float4 w2 = ((const float4*)W2)[lane];
    float z = fmaxf(acc.x + b.x, 0.f) * w2.x + fmaxf(acc.y + b.y, 0.f) * w2.y +
              fmaxf(acc.z + b.z, 0.f) * w2.z + fmaxf(acc.w + b.w, 0.f) * w2.w;
#pragma unroll
    for (int o = 16; o; o >>= 1) z += __shfl_down_sync(0xFFFFFFFFu, z, o);
    if (lane == 0) g_zd[node] = z * di;
}

// ---------------- layer 2 aggregation (thread per node) ----------------
__global__ void k_aggr2(const float* __restrict__ b2, float* __restrict__ out, int n) {
    int i = blockIdx.x * blockDim.x + threadIdx.x;
    if (i >= n) return;
    float acc = g_zd[i];
    int p = g_ptr[i];
    int e = p + g_degE[i];
    for (int j = p; j < e; j++) acc += g_zd[g_esrc[j]];
    out[i] = fmaf(g_dinv[i], acc, b2[0]);
}

extern "C" void kernel_launch(void* const* d_in, const int* in_sizes, int n_in,
                              void* d_out, int out_size) {
    const float* x  = (const float*)d_in[0];
    const void*  ei = d_in[1];
    const float* W1 = (const float*)d_in[2];
    const float* b1 = (const float*)d_in[3];
    const float* W2 = (const float*)d_in[4];
    const float* b2 = (const float*)d_in[5];
    float*       out = (float*)d_out;

    int n = in_sizes[0] / FDIM;   // 50000
    int E = in_sizes[1] / 2;      // 800000
    int nblocks = (n + SCAN_B - 1) / SCAN_B;
    size_t gemm_smem = (FDIM * FDIM + GROWS * FDIM) * sizeof(float);

    // One-time setup (first call is the uncaptured correctness run; by the
    // capture call these already exist, so no unsafe APIs run during capture).
    static cudaStream_t s2 = nullptr;
    static cudaEvent_t evFork = nullptr, evJoin = nullptr;
    if (!s2) {
        cudaStreamCreateWithFlags(&s2, cudaStreamNonBlocking);
        cudaEventCreateWithFlags(&evFork, cudaEventDisableTiming);
        cudaEventCreateWithFlags(&evJoin, cudaEventDisableTiming);
        cudaFuncSetAttribute(k_gemm1, cudaFuncAttributeMaxDynamicSharedMemorySize,
                             (int)gemm_smem);
    }

    // Fork: GEMM1 on s2, CSR build on the main (captured) stream.
    cudaEventRecord(evFork, 0);
    cudaStreamWaitEvent(s2, evFork, 0);
    k_gemm1<<<(n + GROWS - 1) / GROWS, 128, gemm_smem, s2>>>(x, W1, n);
    cudaEventRecord(evJoin, s2);

    k_zero_deg<<<nblocks, SCAN_B>>>((const unsigned long long*)ei, n);
    k_hist<<<(E + 255) / 256, 256>>>(ei, E);
    k_scan1<<<nblocks, SCAN_B>>>(n);
    k_scan2<<<1, 1024>>>(nblocks);
    k_scan3<<<nblocks, SCAN_B>>>(n);
    k_scatter<<<(E + 255) / 256, 256>>>(ei, E);

    // Join: aggr1 needs both h1 (s2) and the CSR (main stream).
    cudaStreamWaitEvent(0, evJoin, 0);
    k_aggr1<<<(n + 7) / 8, 256>>>(b1, W2, n);
    k_aggr2<<<(n + 255) / 256, 256>>>(b2, out, n);
}

// round 5
// speedup vs baseline: 1.8006x; 1.0208x over previous
#include <cuda_runtime.h>
#include <cuda_fp16.h>
#include <math.h>

#define NMAX 50000
#define EMAX 800000
#define FDIM 128
#define SCAN_B 256
#define GROWS 64   // rows per gemm1 block

// Scratch (allocation-free rule: __device__ globals)
__device__ float  g_dinv[NMAX];
__device__ __half g_h1[(size_t)NMAX * FDIM];       // x @ W1, fp16 compressed
__device__ float  g_zd[NMAX];                      // (relu(a1)@W2)*dinv
__device__ int    g_degE[NMAX];                    // edge in-degree (no self-loop)
__device__ int    g_ptr[NMAX];                     // CSR row start
__device__ int    g_fill[NMAX];                    // atomic fill cursor
__device__ int    g_esrc[EMAX];                    // CSR src per incoming edge
__device__ int    g_bsums[1024];
__device__ int    g_is64;

__device__ __forceinline__ int edge_at(const void* ei, int is64, size_t idx) {
    return is64 ? (int)((const long long*)ei)[idx] : ((const int*)ei)[idx];
}

// ---------------- zero degrees + edge dtype probe ----------------
__global__ void k_zero_deg(const unsigned long long* __restrict__ ei, int n) {
    int i = blockIdx.x * blockDim.x + threadIdx.x;
    if (i < n) g_degE[i] = 0;
    if (i == 0) {
        int is64 = 1;
#pragma unroll
        for (int k = 0; k < 8; k++)
            if (ei[k] >= (unsigned long long)NMAX) is64 = 0;
        g_is64 = is64;
    }
}

__global__ void k_hist(const void* __restrict__ ei, int E) {
    int e = blockIdx.x * blockDim.x + threadIdx.x;
    if (e < E) {
        int is64 = g_is64;
        atomicAdd(&g_degE[edge_at(ei, is64, (size_t)E + e)], 1);
    }
}

// ---------------- 2-level exclusive scan ----------------
__global__ void k_scan1(int n) {
    __shared__ int sm[SCAN_B];
    int i = blockIdx.x * SCAN_B + threadIdx.x;
    int v = (i < n) ? g_degE[i] : 0;
    sm[threadIdx.x] = v;
    __syncthreads();
#pragma unroll
    for (int off = 1; off < SCAN_B; off <<= 1) {
        int t = (threadIdx.x >= off) ? sm[threadIdx.x - off] : 0;
        __syncthreads();
        sm[threadIdx.x] += t;
        __syncthreads();
    }
    if (i < n) g_ptr[i] = sm[threadIdx.x];            // inclusive within block
    if (threadIdx.x == SCAN_B - 1) g_bsums[blockIdx.x] = sm[threadIdx.x];
}

__global__ void k_scan2(int nblocks) {
    __shared__ int sm[1024];
    int t = threadIdx.x;
    sm[t] = (t < nblocks) ? g_bsums[t] : 0;
    __syncthreads();
#pragma unroll
    for (int off = 1; off < 1024; off <<= 1) {
        int v = (t >= off) ? sm[t - off] : 0;
        __syncthreads();
        sm[t] += v;
        __syncthreads();
    }
    if (t < nblocks) g_bsums[t] = sm[t];              // inclusive
}

__global__ void k_scan3(int n) {
    int i = blockIdx.x * SCAN_B + threadIdx.x;
    if (i >= n) return;
    int off = (blockIdx.x > 0) ? g_bsums[blockIdx.x - 1] : 0;
    int d = g_degE[i];
    int start = off + g_ptr[i] - d;                   // exclusive
    g_ptr[i] = start;
    g_fill[i] = start;
    g_dinv[i] = rsqrtf((float)(d + 1));               // +1 self-loop
}

// ---------------- CSR scatter fill ----------------
__global__ void k_scatter(const void* __restrict__ ei, int E) {
    int e = blockIdx.x * blockDim.x + threadIdx.x;
    if (e >= E) return;
    int is64 = g_is64;
    int src = edge_at(ei, is64, (size_t)e);
    int dst = edge_at(ei, is64, (size_t)E + e);
    int pos = atomicAdd(&g_fill[dst], 1);
    g_esrc[pos] = src;
}

// ---------------- GEMM1: h1 = x @ W1 (64 rows/block, fp16 out) ----------------
__global__ void k_gemm1(const float* __restrict__ x, const float* __restrict__ W, int n) {
    extern __shared__ float sm[];
    float* Ws = sm;                  // 128*128
    float* xs = sm + FDIM * FDIM;    // GROWS*128
    int tid = threadIdx.x;

    const float4* W4 = (const float4*)W;
    float4* Ws4 = (float4*)Ws;
#pragma unroll
    for (int i = 0; i < 32; i++) Ws4[i * 128 + tid] = W4[i * 128 + tid];

    int row0 = blockIdx.x * GROWS;
    int nrows = n - row0; if (nrows > GROWS) nrows = GROWS;

    const float4* x4 = (const float4*)(x + (size_t)row0 * FDIM);
    float4* xs4 = (float4*)xs;
    for (int i = tid; i < nrows * 32; i += 128) xs4[i] = x4[i];
    __syncthreads();

    int j = tid;
    for (int r = 0; r < nrows; r += 4) {
        float a0 = 0.f, a1 = 0.f, a2 = 0.f, a3 = 0.f;
#pragma unroll
        for (int k = 0; k < FDIM; k += 4) {
            float4 v0 = xs4[((r + 0) * FDIM + k) >> 2];
            float4 v1 = xs4[((r + 1) * FDIM + k) >> 2];
            float4 v2 = xs4[((r + 2) * FDIM + k) >> 2];
            float4 v3 = xs4[((r + 3) * FDIM + k) >> 2];
            float w0 = Ws[(k + 0) * FDIM + j];
            float w1 = Ws[(k + 1) * FDIM + j];
            float w2 = Ws[(k + 2) * FDIM + j];
            float w3 = Ws[(k + 3) * FDIM + j];
            a0 += v0.x * w0 + v0.y * w1 + v0.z * w2 + v0.w * w3;
            a1 += v1.x * w0 + v1.y * w1 + v1.z * w2 + v1.w * w3;
            a2 += v2.x * w0 + v2.y * w1 + v2.z * w2 + v2.w * w3;
            a3 += v3.x * w0 + v3.y * w1 + v3.z * w2 + v3.w * w3;
        }
        if (r + 0 < nrows) g_h1[(size_t)(row0 + r + 0) * FDIM + j] = __float2half_rn(a0);
        if (r + 1 < nrows) g_h1[(size_t)(row0 + r + 1) * FDIM + j] = __float2half_rn(a1);
        if (r + 2 < nrows) g_h1[(size_t)(row0 + r + 2) * FDIM + j] = __float2half_rn(a2);
        if (r + 3 < nrows) g_h1[(size_t)(row0 + r + 3) * FDIM + j] = __float2half_rn(a3);
    }
}

// ---------------- fused aggregate1 + bias + relu + layer2 dot ----------------
// warp per node; lane handles 4 channels (one uint2 = 2x half2 per row).
__device__ __forceinline__ void acc_row(float4& acc, const uint2 v, float w) {
    float2 f0 = __half22float2(*(const half2*)&v.x);
    float2 f1 = __half22float2(*(const half2*)&v.y);
    acc.x = fmaf(f0.x, w, acc.x);
    acc.y = fmaf(f0.y, w, acc.y);
    acc.z = fmaf(f1.x, w, acc.z);
    acc.w = fmaf(f1.y, w, acc.w);
}

__global__ void k_aggr1(const float* __restrict__ b1, const float* __restrict__ W2, int n) {
    int node = (blockIdx.x * blockDim.x + threadIdx.x) >> 5;
    int lane = threadIdx.x & 31;
    if (node >= n) return;

    float di = g_dinv[node];
    float4 acc = make_float4(0.f, 0.f, 0.f, 0.f);
    {
        uint2 v = ((const uint2*)(g_h1 + (size_t)node * FDIM))[lane];
        acc_row(acc, v, di * di);
    }

    int p = g_ptr[node];
    int e = p + g_degE[node];
    int j = p;
    for (; j + 4 <= e; j += 4) {
        int s0 = g_esrc[j + 0];
        int s1 = g_esrc[j + 1];
        int s2 = g_esrc[j + 2];
        int s3 = g_esrc[j + 3];
        float w0 = g_dinv[s0] * di;
        float w1 = g_dinv[s1] * di;
        float w2 = g_dinv[s2] * di;
        float w3 = g_dinv[s3] * di;
        uint2 v0 = ((const uint2*)(g_h1 + (size_t)s0 * FDIM))[lane];
        uint2 v1 = ((const uint2*)(g_h1 + (size_t)s1 * FDIM))[lane];
        uint2 v2 = ((const uint2*)(g_h1 + (size_t)s2 * FDIM))[lane];
        uint2 v3 = ((const uint2*)(g_h1 + (size_t)s3 * FDIM))[lane];
        acc_row(acc, v0, w0);
        acc_row(acc, v1, w1);
        acc_row(acc, v2, w2);
        acc_row(acc, v3, w3);
    }
    for (; j < e; j++) {
        int src = g_esrc[j];
        float w = g_dinv[src] * di;
        uint2 v = ((const uint2*)(g_h1 + (size_t)src * FDIM))[lane];
        acc_row(acc, v, w);
    }

    float4 b = ((const float4*)b1)[lane];
    float4 w2 = ((const float4*)W2)[lane];
    float z = fmaxf(acc.x + b.x, 0.f) * w2.x + fmaxf(acc.y + b.y, 0.f) * w2.y +
              fmaxf(acc.z + b.z, 0.f) * w2.z + fmaxf(acc.w + b.w, 0.f) * w2.w;
#pragma unroll
    for (int o = 16; o; o >>= 1) z += __shfl_down_sync(0xFFFFFFFFu, z, o);
    if (lane == 0) g_zd[node] = z * di;
}

// ---------------- layer 2 aggregation (thread per node) ----------------
__global__ void k_aggr2(const float* __restrict__ b2, float* __restrict__ out, int n) {
    int i = blockIdx.x * blockDim.x + threadIdx.x;
    if (i >= n) return;
    float acc = g_zd[i];
    int p = g_ptr[i];
    int e = p + g_degE[i];
    for (int j = p; j < e; j++) acc += g_zd[g_esrc[j]];
    out[i] = fmaf(g_dinv[i], acc, b2[0]);
}

extern "C" void kernel_launch(void* const* d_in, const int* in_sizes, int n_in,
                              void* d_out, int out_size) {
    const float* x  = (const float*)d_in[0];
    const void*  ei = d_in[1];
    const float* W1 = (const float*)d_in[2];
    const float* b1 = (const float*)d_in[3];
    const float* W2 = (const float*)d_in[4];
    const float* b2 = (const float*)d_in[5];
    float*       out = (float*)d_out;

    int n = in_sizes[0] / FDIM;   // 50000
    int E = in_sizes[1] / 2;      // 800000
    int nblocks = (n + SCAN_B - 1) / SCAN_B;
    size_t gemm_smem = (FDIM * FDIM + GROWS * FDIM) * sizeof(float);

    // One-time setup outside graph capture (first call is the uncaptured
    // correctness run; objects persist for the capture call).
    static cudaStream_t s2 = nullptr;
    static cudaEvent_t evFork = nullptr, evJoin = nullptr;
    if (!s2) {
        cudaStreamCreateWithFlags(&s2, cudaStreamNonBlocking);
        cudaEventCreateWithFlags(&evFork, cudaEventDisableTiming);
        cudaEventCreateWithFlags(&evJoin, cudaEventDisableTiming);
        cudaFuncSetAttribute(k_gemm1, cudaFuncAttributeMaxDynamicSharedMemorySize,
                             (int)gemm_smem);
    }

    // Fork: GEMM1 on s2, CSR build on the main (captured) stream.
    cudaEventRecord(evFork, 0);
    cudaStreamWaitEvent(s2, evFork, 0);
    k_gemm1<<<(n + GROWS - 1) / GROWS, 128, gemm_smem, s2>>>(x, W1, n);
    cudaEventRecord(evJoin, s2);

    k_zero_deg<<<nblocks, SCAN_B>>>((const unsigned long long*)ei, n);
    k_hist<<<(E + 255) / 256, 256>>>(ei, E);
    k_scan1<<<nblocks, SCAN_B>>>(n);
    k_scan2<<<1, 1024>>>(nblocks);
    k_scan3<<<nblocks, SCAN_B>>>(n);
    k_scatter<<<(E + 255) / 256, 256>>>(ei, E);

    // Join: aggr1 needs both h1 (s2) and the CSR (main stream).
    cudaStreamWaitEvent(0, evJoin, 0);
    k_aggr1<<<(n + 7) / 8, 256>>>(b1, W2, n);
    k_aggr2<<<(n + 255) / 256, 256>>>(b2, out, n);
}